// round 1
// baseline (speedup 1.0000x reference)
#include <cuda_runtime.h>

#define QB       128     // queries per CTA
#define NTHREADS 256
#define CAP      2048    // worklist capacity (expected ~320)
#define KK       27      // kernel points
#define CH       64      // CIN == COUT

__global__ __launch_bounds__(NTHREADS) void kpconv_kernel(
    const float* __restrict__ q_pts,   // [N,3]
    const float* __restrict__ s_pts,   // [M,3]
    const int*   __restrict__ inds,    // [N,32]
    const float* __restrict__ x,       // [M,64]
    const float* __restrict__ W,       // [27,64,64]
    const float* __restrict__ kpts,    // [27,3]
    float* __restrict__ out,           // [N,64]
    int N, int M)
{
    extern __shared__ float sm[];
    float* out_acc = sm;                       // QB*64      fp32
    float* Wtile   = out_acc + QB * CH;        // 4096       fp32
    float* qp      = Wtile + 4096;             // QB*3
    float* kp      = qp + QB * 3;              // 84 (27*3 padded)
    float* ew      = kp + 84;                  // CAP
    float* sew     = ew + CAP;                 // CAP
    int*   eind    = (int*)(sew + CAP);        // CAP
    int*   seind   = eind + CAP;               // CAP
    int*   kcnt    = seind + CAP;              // KK
    int*   kstart  = kcnt + KK;                // KK+1
    int*   koff    = kstart + KK + 1;          // KK
    int*   cntp    = koff + KK;                // 1
    unsigned short* eqk  = (unsigned short*)(cntp + 1);  // CAP
    unsigned short* seqk = eqk + CAP;                    // CAP

    const int tid   = threadIdx.x;
    const int qbase = blockIdx.x * QB;

    // ---- init ----
    for (int i = tid; i < QB * CH; i += NTHREADS) out_acc[i] = 0.f;
    for (int i = tid; i < QB * 3; i += NTHREADS) {
        int gi = qbase * 3 + i;
        qp[i] = (gi < N * 3) ? q_pts[gi] : 0.f;
    }
    for (int i = tid; i < KK * 3; i += NTHREADS) kp[i] = kpts[i];
    if (tid < KK) kcnt[tid] = 0;
    if (tid == 0) *cntp = 0;
    __syncthreads();

    // skip bound: weight_k > 0 requires |nb - kp_k| < EXT; max|kp| = RADIUS = 1
    // => |nb| < 1 + EXT = 1.8660254  (small safety margin added)
    const float TH2     = 1.8675f * 1.8675f;
    const float INV_EXT = 1.15470053837925f;   // 1 / (RADIUS/(KS-1)*sqrt(3))

    // ---- phase 1: scan pairs, build compact worklist ----
    for (int p = tid; p < QB * 32; p += NTHREADS) {
        int q  = p >> 5, h = p & 31;
        int gq = qbase + q;
        if (gq >= N) continue;
        int ind = inds[gq * 32 + h];
        if ((unsigned)ind >= (unsigned)M) continue;   // shadow neighbor
        float dx = s_pts[ind * 3 + 0] - qp[q * 3 + 0];
        float dy = s_pts[ind * 3 + 1] - qp[q * 3 + 1];
        float dz = s_pts[ind * 3 + 2] - qp[q * 3 + 2];
        float d2 = dx * dx + dy * dy + dz * dz;
        if (d2 >= TH2) continue;                      // ~98% of pairs exit here
        #pragma unroll
        for (int k = 0; k < KK; k++) {
            float ex = dx - kp[k * 3 + 0];
            float ey = dy - kp[k * 3 + 1];
            float ez = dz - kp[k * 3 + 2];
            float dd = ex * ex + ey * ey + ez * ez;
            float w  = 1.f - sqrtf(dd) * INV_EXT;
            if (w > 0.f) {
                int e = atomicAdd(cntp, 1);
                if (e < CAP) {
                    eqk[e]  = (unsigned short)((q << 5) | k);
                    ew[e]   = w;
                    eind[e] = ind;
                    atomicAdd(&kcnt[k], 1);
                } else {
                    // correctness fallback (statistically unreachable):
                    // direct matvec with global W, atomic accumulate
                    const float* xr = x + (size_t)ind * CH;
                    const float* wk = W + (size_t)k * CH * CH;
                    for (int o = 0; o < CH; o++) {
                        float a = 0.f;
                        for (int c = 0; c < CH; c++) a += xr[c] * wk[c * CH + o];
                        atomicAdd(&out_acc[q * CH + o], w * a);
                    }
                }
            }
        }
    }
    __syncthreads();

    // ---- phase 2: counting sort by k ----
    int ne = min(*cntp, CAP);
    if (tid == 0) {
        int s = 0;
        for (int k = 0; k < KK; k++) { kstart[k] = s; koff[k] = s; s += kcnt[k]; }
        kstart[KK] = s;
    }
    __syncthreads();
    for (int e = tid; e < ne; e += NTHREADS) {
        int k   = eqk[e] & 31;
        int pos = atomicAdd(&koff[k], 1);
        seqk[pos]  = eqk[e];
        sew[pos]   = ew[e];
        seind[pos] = eind[e];
    }
    __syncthreads();

    // ---- phase 3: per-k, stage W[k] in smem, matvec per entry ----
    // Warp w owns all queries with (q & 7) == w  -> no atomics on out_acc.
    const int wid = tid >> 5, lane = tid & 31;
    for (int k = 0; k < KK; k++) {
        int e0 = kstart[k], e1 = kstart[k + 1];
        if (e0 == e1) continue;                 // uniform branch
        __syncthreads();                        // prior k done reading Wtile
        {
            const float4* src = (const float4*)(W + (size_t)k * CH * CH);
            float4*       dst = (float4*)Wtile;
            for (int i = tid; i < (CH * CH) / 4; i += NTHREADS) dst[i] = src[i];
        }
        __syncthreads();
        for (int e = e0; e < e1; e++) {
            int qk = seqk[e];
            int q  = qk >> 5;
            if ((q & 7) != wid) continue;       // warp-uniform ownership test
            float w   = sew[e];
            int   ind = seind[e];
            const float4* xr = (const float4*)(x + (size_t)ind * CH);
            float a0 = 0.f, a1 = 0.f;
            #pragma unroll
            for (int c4 = 0; c4 < 16; c4++) {
                float4 xv = __ldg(xr + c4);     // broadcast, L1-hit
                const float* wr = Wtile + c4 * 4 * CH;
                a0 += xv.x * wr[lane];            a1 += xv.x * wr[lane + 32];
                a0 += xv.y * wr[CH + lane];       a1 += xv.y * wr[CH + lane + 32];
                a0 += xv.z * wr[2 * CH + lane];   a1 += xv.z * wr[2 * CH + lane + 32];
                a0 += xv.w * wr[3 * CH + lane];   a1 += xv.w * wr[3 * CH + lane + 32];
            }
            out_acc[q * CH + lane]      += w * a0;   // race-free: warp owns q
            out_acc[q * CH + lane + 32] += w * a1;
        }
    }
    __syncthreads();

    // ---- write out (all rows, including zeros — d_out is poisoned) ----
    for (int i = tid; i < QB * CH; i += NTHREADS) {
        int q = i >> 6;
        if (qbase + q < N) out[(size_t)(qbase + q) * CH + (i & 63)] = out_acc[i];
    }
}

static int smem_bytes() {
    int f = QB * CH + 4096 + QB * 3 + 84 + CAP + CAP;   // floats
    int i = CAP + CAP + KK + (KK + 1) + KK + 1;         // ints
    int s = CAP + CAP;                                  // ushorts
    return f * 4 + i * 4 + s * 2;
}

extern "C" void kernel_launch(void* const* d_in, const int* in_sizes, int n_in,
                              void* d_out, int out_size) {
    const float* q_pts = (const float*)d_in[0];
    const float* s_pts = (const float*)d_in[1];
    const int*   inds  = (const int*)d_in[2];
    const float* x     = (const float*)d_in[3];
    const float* W     = (const float*)d_in[4];
    const float* kpts  = (const float*)d_in[5];
    float*       out   = (float*)d_out;

    int N = in_sizes[0] / 3;
    int M = in_sizes[1] / 3;

    int smem = smem_bytes();
    cudaFuncSetAttribute(kpconv_kernel,
                         cudaFuncAttributeMaxDynamicSharedMemorySize, smem);
    int grid = (N + QB - 1) / QB;
    kpconv_kernel<<<grid, NTHREADS, smem>>>(q_pts, s_pts, inds, x, W, kpts,
                                            out, N, M);
}